// round 5
// baseline (speedup 1.0000x reference)
#include <cuda_runtime.h>
#include <cuda_fp16.h>
#include <math.h>

#define T_LEN  (1 << 20)
#define CPT    16                  // elements per thread
#define BLK    256
#define CHUNK  (BLK * CPT)         // 4096
#define NCHUNK (T_LEN / CHUNK)     // 256
#define NB     4
#define HMIN   6.103515625e-05f    // fp16 min normal; clip floor (>= 1e-8 semantics, see notes)
#define P3BLKS 64

struct Consts {
    float a[6];   // 1 - c   (k 0..2 short, 3..5 long)
    float aC[6];  // a^CPT
    float aL[6];  // a^CHUNK
};

// Static device scratch (no cudaMalloc allowed)
__device__ __align__(128) float g_tot[2][NB][NCHUNK][16];  // per-family chunk totals (12 used)
__device__ int   g_flag[2][NB][NCHUNK];
__device__ __align__(16) __half g_A[8][3][T_LEN];          // short log-diff, swizzled addr(t)
__device__ __align__(16) __half g_C[8][3][T_LEN];          // long  log-diff, stored pre-shifted
__device__ float g_part[24 * P3BLKS];

__device__ __forceinline__ int ld_acquire(const int* p) {
    int v;
    asm volatile("ld.acquire.gpu.b32 %0, [%1];" : "=r"(v) : "l"(p) : "memory");
    return v;
}
__device__ __forceinline__ void st_release(int* p, int v) {
    asm volatile("st.release.gpu.b32 [%0], %1;" :: "l"(p), "r"(v) : "memory");
}

// out[k] = base[k]^e via squaring ladder (e <= 255)
__device__ __forceinline__ void pow3(float* out, const float* base, int e) {
#pragma unroll
    for (int k = 0; k < 3; k++) {
        float p = 1.0f, bb = base[k];
        int ee = e;
#pragma unroll
        for (int bit = 0; bit < 8; bit++) { if (ee & 1) p *= bb; bb *= bb; ee >>= 1; }
        out[k] = p;
    }
}

// 12 z-chains (c factored out; cancels in log-differences):
// z[0..2]=pred-mid, z[3..5]=true-mid, z[6..8]=pred-side, z[9..11]=true-side
__device__ __forceinline__ void chain12(float* z, const float* A3, float2 fa, float2 fb) {
#pragma unroll
    for (int k = 0; k < 3; k++) {
        z[k]     = fmaf(A3[k], z[k],     fa.x);
        z[3 + k] = fmaf(A3[k], z[3 + k], fa.y);
        z[6 + k] = fmaf(A3[k], z[6 + k], fb.x);
        z[9 + k] = fmaf(A3[k], z[9 + k], fb.y);
    }
}

__global__ void clear_kernel() {
    int i = blockIdx.x * 1024 + threadIdx.x;
    if (i < 2 * NB * NCHUNK) ((int*)g_flag)[i] = 0;
}

__global__ __launch_bounds__(BLK) void fused_kernel(const float* __restrict__ xp,
                                                    const float* __restrict__ xt, Consts K,
                                                    int sh0, int sh1, int sh2) {
    __shared__ float wagg[12][8];                 // exclusive warp prefixes
    __shared__ float cagg[12][8];                 // lookback cross-warp partials
    __shared__ __align__(16) float tot_s[12];     // block totals
    __shared__ float cb_s[12];                    // chunk carry-in

    int g = blockIdx.x, b = blockIdx.y, f = blockIdx.z, tid = threadIdx.x;
    int lane = tid & 31, warp = tid >> 5;

    float A3[3], AC3[3], AL3[3];
#pragma unroll
    for (int k = 0; k < 3; k++) {
        A3[k]  = K.a[f * 3 + k];
        AC3[k] = K.aC[f * 3 + k];
        AL3[k] = K.aL[f * 3 + k];
    }

    size_t base = (size_t)g * CHUNK + (size_t)tid * CPT;
    const float4* p0 = (const float4*)(xp + (size_t)(b * 2 + 0) * T_LEN + base);
    const float4* p1 = (const float4*)(xp + (size_t)(b * 2 + 1) * T_LEN + base);
    const float4* q0 = (const float4*)(xt + (size_t)(b * 2 + 0) * T_LEN + base);
    const float4* q1 = (const float4*)(xt + (size_t)(b * 2 + 1) * T_LEN + base);

    // ── Phase A: read input once (streaming), quantize v to half2 regs, run 12 chains ──
    __half2 v2a[CPT];   // (v_pred_mid, v_true_mid) per element
    __half2 v2b[CPT];   // (v_pred_side, v_true_side)
    float y[12];
#pragma unroll
    for (int c = 0; c < 12; c++) y[c] = 0.0f;

#pragma unroll
    for (int jj = 0; jj < CPT / 4; jj++) {
        float4 a0 = __ldcs(p0 + jj), a1 = __ldcs(p1 + jj);
        float4 b0 = __ldcs(q0 + jj), b1 = __ldcs(q1 + jj);
#define PH_A(e, el) {                                                            \
        float sm = a0.e + a1.e, sd = a0.e - a1.e;                                \
        float tm = b0.e + b1.e, td = b0.e - b1.e;                                \
        __half2 va = __floats2half2_rn(fmaxf(0.5f * sm * sm, HMIN),              \
                                       fmaxf(0.5f * tm * tm, HMIN));             \
        __half2 vb = __floats2half2_rn(fmaxf(0.5f * sd * sd, HMIN),              \
                                       fmaxf(0.5f * td * td, HMIN));             \
        v2a[el] = va; v2b[el] = vb;                                              \
        chain12(y, A3, __half22float2(va), __half22float2(vb)); }
        PH_A(x, jj * 4 + 0) PH_A(y, jj * 4 + 1) PH_A(z, jj * 4 + 2) PH_A(w, jj * 4 + 3)
#undef PH_A
    }

    // ── Warp decayed scan over 12 channels ──
    float pw[3];
#pragma unroll
    for (int k = 0; k < 3; k++) pw[k] = AC3[k];
#pragma unroll
    for (int off = 1; off < 32; off <<= 1) {
#pragma unroll
        for (int c = 0; c < 12; c++) {
            float up = __shfl_up_sync(0xffffffffu, y[c], off);
            if (lane >= off) y[c] = fmaf(pw[c % 3], up, y[c]);
        }
#pragma unroll
        for (int k = 0; k < 3; k++) pw[k] *= pw[k];   // ends at aC^32
    }
    if (lane == 31) {
#pragma unroll
        for (int c = 0; c < 12; c++) wagg[c][warp] = y[c];
    }
    __syncthreads();
    if (tid < 12) {
        float p = 0.0f, aW = pw[tid % 3];
#pragma unroll
        for (int w = 0; w < 8; w++) {
            float t = wagg[tid][w];
            wagg[tid][w] = p;               // exclusive warp prefix
            p = fmaf(aW, p, t);
        }
        tot_s[tid] = p;                     // block total
    }
    __syncthreads();

    // ── Publish local totals ASAP (before any waiting!) ──
    if (tid == 0) {
        float4* dst = (float4*)g_tot[f][b][g];
#pragma unroll
        for (int q = 0; q < 3; q++) dst[q] = ((float4*)tot_s)[q];
        st_release(&g_flag[f][b][g], 1);
    }

    // ── Thread-exclusive local prefix ──
    float cin[12];
    {
        float alane[3];
        pow3(alane, AC3, lane + 1);
#pragma unroll
        for (int c = 0; c < 12; c++) {
            float P  = wagg[c][warp];
            float bi = fmaf(alane[c % 3], P, y[c]);        // block-inclusive
            float pr = __shfl_up_sync(0xffffffffu, bi, 1);
            cin[c] = (lane == 0) ? P : pr;
        }
    }

    // ── Phase B: decoupled lookback — carry = sum_d aL^d * local(g-1-d) ──
    float contrib[12];
#pragma unroll
    for (int c = 0; c < 12; c++) contrib[c] = 0.0f;
    if (tid < g) {
        int j = g - 1 - tid;
        float wd[3];
        pow3(wd, AL3, tid);
        while (!ld_acquire(&g_flag[f][b][j])) __nanosleep(64);
        const float4* tp = (const float4*)g_tot[f][b][j];
#pragma unroll
        for (int q = 0; q < 3; q++) {
            float4 v4 = __ldcg(tp + q);
            contrib[q * 4 + 0] = wd[(q * 4 + 0) % 3] * v4.x;
            contrib[q * 4 + 1] = wd[(q * 4 + 1) % 3] * v4.y;
            contrib[q * 4 + 2] = wd[(q * 4 + 2) % 3] * v4.z;
            contrib[q * 4 + 3] = wd[(q * 4 + 3) % 3] * v4.w;
        }
    }
#pragma unroll
    for (int off = 16; off > 0; off >>= 1) {
#pragma unroll
        for (int c = 0; c < 12; c++)
            contrib[c] += __shfl_xor_sync(0xffffffffu, contrib[c], off);
    }
    if (lane == 0) {
#pragma unroll
        for (int c = 0; c < 12; c++) cagg[c][warp] = contrib[c];
    }
    __syncthreads();
    if (tid < 12) {
        float s = 0.0f;
#pragma unroll
        for (int w = 0; w < 8; w++) s += cagg[tid][w];
        cb_s[tid] = s;
    }
    __syncthreads();

    {   // fold chunk carry: cin += aC^tid * carry
        float atid[3];
        pow3(atid, AC3, tid);
#pragma unroll
        for (int c = 0; c < 12; c++) cin[c] = fmaf(atid[c % 3], cb_s[c], cin[c]);
    }

    // ── Phase C: replay chains from register-cached v, emit fp16 log-diffs ──
    int row0 = b * 2, row1 = b * 2 + 1;
    int obase = g * CHUNK;
    int shifts[3] = {sh0, sh1, sh2};

#pragma unroll
    for (int el = 0; el < CPT; el++) {
        chain12(cin, A3, __half22float2(v2a[el]), __half22float2(v2b[el]));
        int addr = obase + el * BLK + tid;
        if (f == 0) {
#pragma unroll
            for (int i = 0; i < 3; i++) {
                g_A[row0][i][addr] = __float2half(__log2f(cin[i])     - __log2f(cin[3 + i]));
                g_A[row1][i][addr] = __float2half(__log2f(cin[6 + i]) - __log2f(cin[9 + i]));
            }
        } else {
            int t = obase + tid * CPT + el;
#pragma unroll
            for (int i = 0; i < 3; i++) {
                int t2 = (t - shifts[i]) & (T_LEN - 1);
                int caddr = (t2 & ~(CHUNK - 1)) | ((t2 & (CPT - 1)) << 8)
                          | ((t2 & (CHUNK - 1)) >> 4);
                g_C[row0][i][caddr] = __float2half(__log2f(cin[i])     - __log2f(cin[3 + i]));
                g_C[row1][i][caddr] = __float2half(__log2f(cin[6 + i]) - __log2f(cin[9 + i]));
            }
        }
    }
}

// Both streams linear + 16B aligned (long side pre-shifted at write time).
__global__ __launch_bounds__(256) void pass3_kernel() {
    int tid = threadIdx.x;
    int combo = blockIdx.y;               // 24 = 8 rows x 3 pairs
    int row = combo / 3, i = combo % 3;
    const uint4* __restrict__ A = (const uint4*)g_A[row][i];
    const uint4* __restrict__ C = (const uint4*)g_C[row][i];
    const int n = T_LEN / 8;
    float acc = 0.0f;
    for (int v = blockIdx.x * 256 + tid; v < n; v += P3BLKS * 256) {
        uint4 a = __ldcs(A + v), c = __ldcs(C + v);
        const __half2* ha = (const __half2*)&a;
        const __half2* hc = (const __half2*)&c;
#pragma unroll
        for (int q = 0; q < 4; q++) {
            __half2 d = __habs2(__hsub2(ha[q], hc[q]));
            float2 fl = __half22float2(d);
            acc += fl.x + fl.y;
        }
    }
    __shared__ float sh[256];
    sh[tid] = acc;
    __syncthreads();
    for (int s = 128; s > 0; s >>= 1) {
        if (tid < s) sh[tid] += sh[tid + s];
        __syncthreads();
    }
    if (tid == 0) g_part[combo * P3BLKS + blockIdx.x] = sh[0];
}

__global__ void final_kernel(float* __restrict__ out) {
    __shared__ float sh[1024];
    int tid = threadIdx.x;
    float v = 0.0f;
    for (int i = tid; i < 24 * P3BLKS; i += 1024) v += g_part[i];
    sh[tid] = v;
    __syncthreads();
    for (int s = 512; s > 0; s >>= 1) {
        if (tid < s) sh[tid] += sh[tid + s];
        __syncthreads();
    }
    if (tid == 0)
        out[0] = (float)((double)sh[0] * 0.69314718055994530942 / (8.0 * (double)T_LEN));
}

extern "C" void kernel_launch(void* const* d_in, const int* in_sizes, int n_in,
                              void* d_out, int out_size) {
    const float* xp = (const float*)d_in[0];
    const float* xt = (const float*)d_in[1];
    (void)in_sizes; (void)n_in; (void)out_size;

    Consts K;
    const double sr = 44100.0;
    const double s_taus[3] = {10.0, 50.0, 100.0};
    const double l_taus[3] = {500.0, 1500.0, 3000.0};
    int shifts[3];
    float cco[6];
    for (int i = 0; i < 3; i++) {
        cco[i]     = (float)(1.0 - exp(-2200.0 / (s_taus[i] * sr)));
        cco[3 + i] = (float)(1.0 - exp(-2200.0 / (l_taus[i] * sr)));
        shifts[i]  = (int)(sr * (l_taus[i] - s_taus[i]) * 0.0005);
    }
    for (int k = 0; k < 6; k++) {
        K.a[k]  = 1.0f - cco[k];
        K.aC[k] = (float)pow((double)K.a[k], (double)CPT);
        K.aL[k] = (float)pow((double)K.a[k], (double)CHUNK);
    }

    clear_kernel<<<2, 1024>>>();
    dim3 grid(NCHUNK, NB, 2);
    fused_kernel<<<grid, BLK>>>(xp, xt, K, shifts[0], shifts[1], shifts[2]);
    dim3 g3(P3BLKS, 24);
    pass3_kernel<<<g3, 256>>>();
    final_kernel<<<1, 1024>>>((float*)d_out);
}

// round 6
// speedup vs baseline: 1.1779x; 1.1779x over previous
#include <cuda_runtime.h>
#include <cuda_fp16.h>
#include <math.h>

#define T_LEN  (1 << 20)
#define CPT    16                  // elements per thread
#define BLK    256
#define CHUNK  (BLK * CPT)         // 4096
#define NCHUNK (T_LEN / CHUNK)     // 256
#define NB     4
#define HMIN   6.103515625e-05f    // fp16 min normal clip floor (validated R4: rel_err 4.4e-5)
#define P3BLKS 64

struct Consts {
    float a[6];   // 1 - c   (k 0..2 short, 3..5 long)
    float aC[6];  // a^CPT
    float aL[6];  // a^CHUNK
};

// Static device scratch (no cudaMalloc allowed)
__device__ __align__(128) float g_tot[NB][NCHUNK][32];   // chunk-local totals (24 used), 128B padded
__device__ int   g_flag[NB][NCHUNK];
__device__ __align__(16) __half g_A[8][3][T_LEN];        // short log-diff, swizzled addr(t)
__device__ __align__(16) __half g_C[8][3][T_LEN];        // long  log-diff, stored pre-shifted
__device__ float g_part[24 * P3BLKS];

__device__ __forceinline__ int ld_acquire(const int* p) {
    int v;
    asm volatile("ld.acquire.gpu.b32 %0, [%1];" : "=r"(v) : "l"(p) : "memory");
    return v;
}
__device__ __forceinline__ void st_release(int* p, int v) {
    asm volatile("st.release.gpu.b32 [%0], %1;" :: "l"(p), "r"(v) : "memory");
}

// out[k] = base[k]^e via exact squaring ladder (e <= 255)
__device__ __forceinline__ void pow_ladder(float* out, const float* base, int e) {
#pragma unroll
    for (int k = 0; k < 6; k++) {
        float p = 1.0f, bb = base[k];
        int ee = e;
#pragma unroll
        for (int bit = 0; bit < 8; bit++) { if (ee & 1) p *= bb; bb *= bb; ee >>= 1; }
        out[k] = p;
    }
}

// 24 z-chains (c factored out; cancels in log-differences):
// ch = grp*6 + k; grp 0=pred-mid 1=true-mid 2=pred-side 3=true-side; k 0..2 short, 3..5 long
__device__ __forceinline__ void chain24(float* z, const Consts& K,
                                        float vpm, float vtm, float vps, float vts) {
#pragma unroll
    for (int k = 0; k < 6; k++) {
        z[k]      = fmaf(K.a[k], z[k],      vpm);
        z[6 + k]  = fmaf(K.a[k], z[6 + k],  vtm);
        z[12 + k] = fmaf(K.a[k], z[12 + k], vps);
        z[18 + k] = fmaf(K.a[k], z[18 + k], vts);
    }
}

__global__ void clear_kernel() {
    int i = threadIdx.x;
    if (i < NB * NCHUNK) ((int*)g_flag)[i] = 0;
}

__global__ __launch_bounds__(BLK) void fused_kernel(const float* __restrict__ xp,
                                                    const float* __restrict__ xt, Consts K,
                                                    int sh0, int sh1, int sh2) {
    __shared__ float wagg[24][8];                 // exclusive warp prefixes
    __shared__ float cagg[24][8];                 // lookback cross-warp partials
    __shared__ __align__(16) float tot_s[24];     // block totals
    __shared__ float cb_s[24];                    // chunk carry-in

    int g = blockIdx.x, b = blockIdx.y, tid = threadIdx.x;
    int lane = tid & 31, warp = tid >> 5;
    size_t base = (size_t)g * CHUNK + (size_t)tid * CPT;
    const float4* p0 = (const float4*)(xp + (size_t)(b * 2 + 0) * T_LEN + base);
    const float4* p1 = (const float4*)(xp + (size_t)(b * 2 + 1) * T_LEN + base);
    const float4* q0 = (const float4*)(xt + (size_t)(b * 2 + 0) * T_LEN + base);
    const float4* q1 = (const float4*)(xt + (size_t)(b * 2 + 1) * T_LEN + base);

    // ── Phase A: read input ONCE, quantize v to half2 registers, run 24 chains ──
    __half2 v2a[CPT];   // (v_pred_mid, v_true_mid)
    __half2 v2b[CPT];   // (v_pred_side, v_true_side)
    float y[24];
#pragma unroll
    for (int c = 0; c < 24; c++) y[c] = 0.0f;

#pragma unroll
    for (int jj = 0; jj < CPT / 4; jj++) {
        float4 a0 = p0[jj], a1 = p1[jj], b0 = q0[jj], b1 = q1[jj];
#define PH_A(e, el) {                                                            \
        float sm = a0.e + a1.e, sd = a0.e - a1.e;                                \
        float tm = b0.e + b1.e, td = b0.e - b1.e;                                \
        __half2 va = __floats2half2_rn(fmaxf(0.5f * sm * sm, HMIN),              \
                                       fmaxf(0.5f * tm * tm, HMIN));             \
        __half2 vb = __floats2half2_rn(fmaxf(0.5f * sd * sd, HMIN),              \
                                       fmaxf(0.5f * td * td, HMIN));             \
        v2a[el] = va; v2b[el] = vb;                                              \
        float2 fa = __half22float2(va), fb = __half22float2(vb);                 \
        chain24(y, K, fa.x, fa.y, fb.x, fb.y); }
        PH_A(x, jj * 4 + 0) PH_A(y, jj * 4 + 1) PH_A(z, jj * 4 + 2) PH_A(w, jj * 4 + 3)
#undef PH_A
    }

    // ── Warp decayed scan over 24 channels ──
    float pw[6];
#pragma unroll
    for (int k = 0; k < 6; k++) pw[k] = K.aC[k];
#pragma unroll
    for (int off = 1; off < 32; off <<= 1) {
#pragma unroll
        for (int c = 0; c < 24; c++) {
            float up = __shfl_up_sync(0xffffffffu, y[c], off);
            if (lane >= off) y[c] = fmaf(pw[c % 6], up, y[c]);
        }
#pragma unroll
        for (int k = 0; k < 6; k++) pw[k] *= pw[k];   // ends at aC^32
    }
    if (lane == 31) {
#pragma unroll
        for (int c = 0; c < 24; c++) wagg[c][warp] = y[c];
    }
    __syncthreads();
    if (tid < 24) {
        float p = 0.0f, aW = pw[tid % 6];
#pragma unroll
        for (int w = 0; w < 8; w++) {
            float t = wagg[tid][w];
            wagg[tid][w] = p;               // exclusive warp prefix
            p = fmaf(aW, p, t);
        }
        tot_s[tid] = p;                     // block total
    }
    __syncthreads();

    // ── Publish local totals ASAP (before any waiting!) ──
    if (tid == 0) {
        float4* dst = (float4*)g_tot[b][g];
#pragma unroll
        for (int q = 0; q < 6; q++) dst[q] = ((float4*)tot_s)[q];
        st_release(&g_flag[b][g], 1);
    }

    // ── Thread-exclusive local prefix (block scope) ──
    float cin[24];
    {
        float alane[6];
        pow_ladder(alane, K.aC, lane + 1);
#pragma unroll
        for (int c = 0; c < 24; c++) {
            float P  = wagg[c][warp];
            float bi = fmaf(alane[c % 6], P, y[c]);        // block-inclusive
            float pr = __shfl_up_sync(0xffffffffu, bi, 1);
            cin[c] = (lane == 0) ? P : pr;
        }
    }

    // ── Phase B: decoupled lookback — carry = sum_d aL^d * local(g-1-d) ──
    float contrib[24];
#pragma unroll
    for (int c = 0; c < 24; c++) contrib[c] = 0.0f;
    if (tid < g) {
        int j = g - 1 - tid;
        float wd[6];
        pow_ladder(wd, K.aL, tid);
        while (!ld_acquire(&g_flag[b][j])) __nanosleep(64);
        const float4* tp = (const float4*)g_tot[b][j];
#pragma unroll
        for (int q = 0; q < 6; q++) {
            float4 v4 = __ldcg(tp + q);
            contrib[q * 4 + 0] = wd[(q * 4 + 0) % 6] * v4.x;
            contrib[q * 4 + 1] = wd[(q * 4 + 1) % 6] * v4.y;
            contrib[q * 4 + 2] = wd[(q * 4 + 2) % 6] * v4.z;
            contrib[q * 4 + 3] = wd[(q * 4 + 3) % 6] * v4.w;
        }
    }
#pragma unroll
    for (int off = 16; off > 0; off >>= 1) {
#pragma unroll
        for (int c = 0; c < 24; c++)
            contrib[c] += __shfl_xor_sync(0xffffffffu, contrib[c], off);
    }
    if (lane == 0) {
#pragma unroll
        for (int c = 0; c < 24; c++) cagg[c][warp] = contrib[c];
    }
    __syncthreads();
    if (tid < 24) {
        float s = 0.0f;
#pragma unroll
        for (int w = 0; w < 8; w++) s += cagg[tid][w];
        cb_s[tid] = s;
    }
    __syncthreads();

    {   // fold chunk carry into per-thread carry-in: cin += aC^tid * carry
        float atid[6];
        pow_ladder(atid, K.aC, tid);
#pragma unroll
        for (int c = 0; c < 24; c++) cin[c] = fmaf(atid[c % 6], cb_s[c], cin[c]);
    }

    // ── Phase C: replay chains from register-cached v, emit fp16 log-diffs ──
    int row0 = b * 2, row1 = b * 2 + 1;
    int obase = g * CHUNK;
    int shifts[3] = {sh0, sh1, sh2};

#pragma unroll
    for (int el = 0; el < CPT; el++) {
        float2 fa = __half22float2(v2a[el]);
        float2 fb = __half22float2(v2b[el]);
        chain24(cin, K, fa.x, fa.y, fb.x, fb.y);
        int addr = obase + el * BLK + tid;
        int t = obase + tid * CPT + el;
#pragma unroll
        for (int i = 0; i < 3; i++) {
            g_A[row0][i][addr] = __float2half(__log2f(cin[i])      - __log2f(cin[6 + i]));
            g_A[row1][i][addr] = __float2half(__log2f(cin[12 + i]) - __log2f(cin[18 + i]));
            int t2 = (t - shifts[i]) & (T_LEN - 1);
            int caddr = (t2 & ~(CHUNK - 1)) | ((t2 & (CPT - 1)) << 8)
                      | ((t2 & (CHUNK - 1)) >> 4);
            g_C[row0][i][caddr] = __float2half(__log2f(cin[3 + i])  - __log2f(cin[9 + i]));
            g_C[row1][i][caddr] = __float2half(__log2f(cin[15 + i]) - __log2f(cin[21 + i]));
        }
    }
}

// Both streams linear + 16B aligned (long side pre-shifted at write time).
__global__ __launch_bounds__(256) void pass3_kernel() {
    int tid = threadIdx.x;
    int combo = blockIdx.y;               // 24 = 8 rows x 3 pairs
    int row = combo / 3, i = combo % 3;
    const uint4* __restrict__ A = (const uint4*)g_A[row][i];
    const uint4* __restrict__ C = (const uint4*)g_C[row][i];
    const int n = T_LEN / 8;
    float acc = 0.0f;
    for (int v = blockIdx.x * 256 + tid; v < n; v += P3BLKS * 256) {
        uint4 a = __ldcs(A + v), c = __ldcs(C + v);
        const __half2* ha = (const __half2*)&a;
        const __half2* hc = (const __half2*)&c;
#pragma unroll
        for (int q = 0; q < 4; q++) {
            __half2 d = __habs2(__hsub2(ha[q], hc[q]));
            float2 fl = __half22float2(d);
            acc += fl.x + fl.y;
        }
    }
    __shared__ float sh[256];
    sh[tid] = acc;
    __syncthreads();
    for (int s = 128; s > 0; s >>= 1) {
        if (tid < s) sh[tid] += sh[tid + s];
        __syncthreads();
    }
    if (tid == 0) g_part[combo * P3BLKS + blockIdx.x] = sh[0];
}

__global__ void final_kernel(float* __restrict__ out) {
    __shared__ float sh[1024];
    int tid = threadIdx.x;
    float v = 0.0f;
    for (int i = tid; i < 24 * P3BLKS; i += 1024) v += g_part[i];
    sh[tid] = v;
    __syncthreads();
    for (int s = 512; s > 0; s >>= 1) {
        if (tid < s) sh[tid] += sh[tid + s];
        __syncthreads();
    }
    if (tid == 0)
        out[0] = (float)((double)sh[0] * 0.69314718055994530942 / (8.0 * (double)T_LEN));
}

extern "C" void kernel_launch(void* const* d_in, const int* in_sizes, int n_in,
                              void* d_out, int out_size) {
    const float* xp = (const float*)d_in[0];
    const float* xt = (const float*)d_in[1];
    (void)in_sizes; (void)n_in; (void)out_size;

    Consts K;
    const double sr = 44100.0;
    const double s_taus[3] = {10.0, 50.0, 100.0};
    const double l_taus[3] = {500.0, 1500.0, 3000.0};
    int shifts[3];
    float cco[6];
    for (int i = 0; i < 3; i++) {
        cco[i]     = (float)(1.0 - exp(-2200.0 / (s_taus[i] * sr)));
        cco[3 + i] = (float)(1.0 - exp(-2200.0 / (l_taus[i] * sr)));
        shifts[i]  = (int)(sr * (l_taus[i] - s_taus[i]) * 0.0005);
    }
    for (int k = 0; k < 6; k++) {
        K.a[k]  = 1.0f - cco[k];
        K.aC[k] = (float)pow((double)K.a[k], (double)CPT);
        K.aL[k] = (float)pow((double)K.a[k], (double)CHUNK);
    }

    clear_kernel<<<1, 1024>>>();
    dim3 grid(NCHUNK, NB);
    fused_kernel<<<grid, BLK>>>(xp, xt, K, shifts[0], shifts[1], shifts[2]);
    dim3 g3(P3BLKS, 24);
    pass3_kernel<<<g3, 256>>>();
    final_kernel<<<1, 1024>>>((float*)d_out);
}